// round 3
// baseline (speedup 1.0000x reference)
#include <cuda_runtime.h>
#include <math.h>

// FFM forward: out[b] = sigmoid( relu(feats@Wd + bd) + sum_{i<j} <v_i[j-1], v_j[i]> )
// v_i[slot] = mean over seq of E_i[slot][x_i[b,s]]   (E_i shape: (5, DIM_i, 16))
// feats[i]  = mean over seq of L_i[x_i[b,s]]

#define WARPS_PER_BLOCK 8
#define BATCH 16384

__constant__ int c_pair_i[15] = {0,0,0,0,0,1,1,1,1,2,2,2,3,3,4};
__constant__ int c_pair_j[15] = {1,2,3,4,5,2,3,4,5,3,4,5,4,5,5};

// STREAM=true: use evict-first (__ldcs) loads for tables with no useful L2
// reuse (E0, E1, E2) so the hot reused tables (E3..E5, L*) stay L2-resident.
template<int SEQN, bool STREAM>
__device__ __forceinline__ void process_field(
    const int* __restrict__ x, const float* __restrict__ E,
    const float* __restrict__ L, int dim, int b, int lane,
    float* __restrict__ v_field,   // [5][16] floats, 16B aligned
    float* __restrict__ feat)
{
    const int slot  = lane >> 2;   // 0..7 (active <5)
    const int chunk = lane & 3;    // float4 chunk within 16-dim row
    float4 acc = make_float4(0.f, 0.f, 0.f, 0.f);
    float  lacc = 0.f;
    const int* xb = x + (size_t)b * SEQN;

#pragma unroll
    for (int s = 0; s < SEQN; ++s) {
        const int idx = __ldg(xb + s);
        if (lane < 20) {
            const float4* p =
                reinterpret_cast<const float4*>(E + ((size_t)slot * dim + idx) * 16) + chunk;
            float4 e = STREAM ? __ldcs(p) : __ldg(p);
            acc.x += e.x; acc.y += e.y; acc.z += e.z; acc.w += e.w;
        } else if (lane == 20) {
            lacc += __ldg(L + idx);
        }
    }
    const float inv = 1.0f / (float)SEQN;
    if (lane < 20) {
        float4 r = make_float4(acc.x * inv, acc.y * inv, acc.z * inv, acc.w * inv);
        *reinterpret_cast<float4*>(v_field + slot * 16 + chunk * 4) = r;
    } else if (lane == 20) {
        *feat = lacc * inv;
    }
}

extern "C" __global__ void __launch_bounds__(WARPS_PER_BLOCK * 32, 4)
ffm_kernel(const int* __restrict__ x0, const int* __restrict__ x1,
           const int* __restrict__ x2, const int* __restrict__ x3,
           const int* __restrict__ x4, const int* __restrict__ x5,
           const float* __restrict__ E0, const float* __restrict__ E1,
           const float* __restrict__ E2, const float* __restrict__ E3,
           const float* __restrict__ E4, const float* __restrict__ E5,
           const float* __restrict__ L0, const float* __restrict__ L1,
           const float* __restrict__ L2, const float* __restrict__ L3,
           const float* __restrict__ L4, const float* __restrict__ L5,
           const float* __restrict__ Wd, const float* __restrict__ bd,
           float* __restrict__ out)
{
    __shared__ __align__(16) float sv[WARPS_PER_BLOCK][6 * 80]; // 6 fields x 5 slots x 16
    __shared__ float sfeat[WARPS_PER_BLOCK][6];

    const int warp = threadIdx.x >> 5;
    const int lane = threadIdx.x & 31;
    const int b = blockIdx.x * WARPS_PER_BLOCK + warp;
    if (b >= BATCH) return;

    float* v    = sv[warp];
    float* feat = sfeat[warp];

    // Heavy gather fields first so their loads issue earliest (deepest MLP).
    process_field<50, true >(x2, E2, L2,  500000, b, lane, v + 2 * 80, feat + 2);
    process_field<20, false>(x3, E3, L3,  100000, b, lane, v + 3 * 80, feat + 3);
    process_field<1 , true >(x0, E0, L0, 1000000, b, lane, v + 0 * 80, feat + 0);
    process_field<1 , true >(x1, E1, L1,  500000, b, lane, v + 1 * 80, feat + 1);
    process_field<1 , false>(x4, E4, L4,   10000, b, lane, v + 4 * 80, feat + 4);
    process_field<1 , false>(x5, E5, L5,    1000, b, lane, v + 5 * 80, feat + 5);

    __syncwarp();

    // fm = sum over 15 pairs (i<j) of dot16(v_i[j-1], v_j[i])
    // 15 pairs x 4 float4-chunks = 60 work items over 32 lanes (2 rounds)
    float partial = 0.f;
#pragma unroll
    for (int r = 0; r < 2; ++r) {
        const int item = lane + r * 32;
        if (item < 60) {
            const int t = item >> 2;
            const int c = item & 3;
            const int i = c_pair_i[t];
            const int j = c_pair_j[t];
            const float4 a  = *reinterpret_cast<const float4*>(v + i * 80 + (j - 1) * 16 + c * 4);
            const float4 bb = *reinterpret_cast<const float4*>(v + j * 80 +  i      * 16 + c * 4);
            partial += a.x * bb.x + a.y * bb.y + a.z * bb.z + a.w * bb.w;
        }
    }
#pragma unroll
    for (int off = 16; off; off >>= 1)
        partial += __shfl_xor_sync(0xffffffffu, partial, off);

    if (lane == 0) {
        float lin = __ldg(bd);
#pragma unroll
        for (int i = 0; i < 6; ++i) lin += feat[i] * __ldg(Wd + i);
        lin = fmaxf(lin, 0.f);
        const float z = lin + partial;
        out[b] = 1.0f / (1.0f + expf(-z));
    }
}

extern "C" void kernel_launch(void* const* d_in, const int* in_sizes, int n_in,
                              void* d_out, int out_size)
{
    // First 6 inputs are x0..x5 in order.
    const int* xs[6];
    for (int i = 0; i < 6; ++i) xs[i] = (const int*)d_in[i];

    // E/L pointers classified by element count (robust to either dict or
    // signature ordering): E_i has 80*DIM_i elements, L_i has DIM_i.
    const float* E[6] = {0,0,0,0,0,0};
    const float* L[6] = {0,0,0,0,0,0};
    const float* Wd = 0;
    const float* bd = 0;
    int ei = 0, li = 0;
    for (int k = 6; k < n_in; ++k) {
        const long long sz = (long long)in_sizes[k];
        const float* p = (const float*)d_in[k];
        if (sz == 80000000LL || sz == 40000000LL || sz == 8000000LL ||
            sz == 800000LL   || sz == 80000LL) {
            if (ei < 6) E[ei++] = p;
        } else if (sz == 1000000LL || sz == 500000LL || sz == 100000LL ||
                   sz == 10000LL   || sz == 1000LL) {
            if (li < 6) L[li++] = p;
        } else if (sz == 6LL) {
            Wd = p;
        } else if (sz == 1LL) {
            bd = p;
        }
    }

    float* out = (float*)d_out;

    const int blocks = BATCH / WARPS_PER_BLOCK; // 2048
    ffm_kernel<<<blocks, WARPS_PER_BLOCK * 32>>>(
        xs[0], xs[1], xs[2], xs[3], xs[4], xs[5],
        E[0], E[1], E[2], E[3], E[4], E[5],
        L[0], L[1], L[2], L[3], L[4], L[5],
        Wd, bd, out);
}

// round 4
// speedup vs baseline: 1.3037x; 1.3037x over previous
#include <cuda_runtime.h>
#include <cuda_pipeline.h>
#include <math.h>

// FFM forward: out[b] = sigmoid( relu(feats@Wd + bd) + sum_{i<j} <v_i[j-1], v_j[i]> )
// v_i[slot] = mean over seq of E_i[slot][x_i[b,s]]   (E_i: (5, DIM_i, 16))
// feats[i]  = mean over seq of L_i[x_i[b,s]]
//
// Heavy fields (i=2: 50 steps, i=3: 20 steps) use a cp.async (LDGSTS) double-
// buffered smem pipeline: loads carry NO destination registers, so memory-level
// parallelism is no longer register-bound (~25 rows in flight per warp).

#define WPB   8
#define BATCH 16384
#define G     5                  // seq steps per pipeline stage
#define STAGE_BYTES (G * 5 * 64) // 5 steps x 5 slots x 64B = 1600

__constant__ int c_pair_i[15] = {0,0,0,0,0,1,1,1,1,2,2,2,3,3,4};
__constant__ int c_pair_j[15] = {1,2,3,4,5,2,3,4,5,3,4,5,4,5,5};

extern "C" __global__ void __launch_bounds__(WPB * 32)
ffm_kernel(const int* __restrict__ x0, const int* __restrict__ x1,
           const int* __restrict__ x2, const int* __restrict__ x3,
           const int* __restrict__ x4, const int* __restrict__ x5,
           const float* __restrict__ E0, const float* __restrict__ E1,
           const float* __restrict__ E2, const float* __restrict__ E3,
           const float* __restrict__ E4, const float* __restrict__ E5,
           const float* __restrict__ L0, const float* __restrict__ L1,
           const float* __restrict__ L2, const float* __restrict__ L3,
           const float* __restrict__ L4, const float* __restrict__ L5,
           const float* __restrict__ Wd, const float* __restrict__ bd,
           float* __restrict__ out)
{
    __shared__ __align__(16) float sv[WPB][6 * 80];            // v vectors
    __shared__ __align__(16) char  stg[WPB][2][STAGE_BYTES];   // pipeline buffers
    __shared__ float sfeat[WPB][8];

    const int warp = threadIdx.x >> 5;
    const int lane = threadIdx.x & 31;
    const int b = blockIdx.x * WPB + warp;
    if (b >= BATCH) return;

    float* v    = sv[warp];
    float* feat = sfeat[warp];
    char*  st0  = stg[warp][0];
    char*  st1  = stg[warp][1];

    const int slot  = lane >> 2;  // 0..7 (active < 5)
    const int chunk = lane & 3;

    // ---------- indices ----------
    const int idx0 = __ldg(x0 + b);
    const int idx1 = __ldg(x1 + b);
    const int idx4 = __ldg(x4 + b);
    const int idx5 = __ldg(x5 + b);
    // field 2: 50 indices, coalesced into 2 regs per lane
    const int i2a = __ldg(x2 + (size_t)b * 50 + lane);
    const int i2b = (lane < 18) ? __ldg(x2 + (size_t)b * 50 + 32 + lane) : 0;
    // field 3: 20 indices
    const int i3  = (lane < 20) ? __ldg(x3 + (size_t)b * 20 + lane) : 0;

    // per-lane gather base pointers (bytes), valid for lane < 20
    const char* gb2 = (const char*)E2 + ((size_t)slot * 500000) * 64 + chunk * 16;
    const char* gb3 = (const char*)E3 + ((size_t)slot * 100000) * 64 + chunk * 16;

    // ---------- single-lookup fields: cp.async straight into final sv slots ----------
    if (lane < 20) {
        const int off = slot * 64 + chunk * 16; // bytes within a field's 5x16 block
        char* vb = (char*)v;
        __pipeline_memcpy_async(vb + 0 * 320 + off,
            (const char*)E0 + ((size_t)slot * 1000000 + idx0) * 64 + chunk * 16, 16);
        __pipeline_memcpy_async(vb + 1 * 320 + off,
            (const char*)E1 + ((size_t)slot * 500000  + idx1) * 64 + chunk * 16, 16);
        __pipeline_memcpy_async(vb + 4 * 320 + off,
            (const char*)E4 + ((size_t)slot * 10000   + idx4) * 64 + chunk * 16, 16);
        __pipeline_memcpy_async(vb + 5 * 320 + off,
            (const char*)E5 + ((size_t)slot * 1000    + idx5) * 64 + chunk * 16, 16);
    } else if (lane == 20) feat[0] = __ldg(L0 + idx0);
    else if (lane == 21)   feat[1] = __ldg(L1 + idx1);
    else if (lane == 22)   feat[4] = __ldg(L4 + idx4);
    else if (lane == 23)   feat[5] = __ldg(L5 + idx5);

    float4 acc2 = make_float4(0.f, 0.f, 0.f, 0.f);
    float4 acc3 = make_float4(0.f, 0.f, 0.f, 0.f);
    float  l2acc = 0.f, l3acc = 0.f;

    // ---------- pipeline stage/consume helpers ----------
    auto stage2 = [&](int g) {
        char* dst = (g & 1) ? st1 : st0;
#pragma unroll
        for (int k = 0; k < G; ++k) {
            const int s = g * G + k;
            const int idx = (s < 32) ? __shfl_sync(0xffffffffu, i2a, s)
                                     : __shfl_sync(0xffffffffu, i2b, s - 32);
            if (lane < 20)
                __pipeline_memcpy_async(dst + k * 320 + lane * 16,
                                        gb2 + (size_t)idx * 64, 16);
            else if (lane >= 24 && (s & 7) == lane - 24)
                l2acc += __ldg(L2 + idx);
        }
        __pipeline_commit();
    };
    auto stage3 = [&](int t) {
        char* dst = (t & 1) ? st1 : st0; // t parity continues g parity (g=10+t)
#pragma unroll
        for (int k = 0; k < G; ++k) {
            const int s = t * G + k;
            const int idx = __shfl_sync(0xffffffffu, i3, s);
            if (lane < 20)
                __pipeline_memcpy_async(dst + k * 320 + lane * 16,
                                        gb3 + (size_t)idx * 64, 16);
            else if (lane >= 24 && (s & 7) == lane - 24)
                l3acc += __ldg(L3 + idx);
        }
        __pipeline_commit();
    };
    auto consume = [&](int parity, float4& acc) {
        const float* src = (const float*)(parity ? st1 : st0);
        if (lane < 20) {
#pragma unroll
            for (int k = 0; k < G; ++k) {
                const float4 e = *(const float4*)(src + k * 80 + lane * 4);
                acc.x += e.x; acc.y += e.y; acc.z += e.z; acc.w += e.w;
            }
        }
    };

    // ---------- main pipeline: field 2 (10 groups), field 3 (4 groups) ----------
    stage2(0);
#pragma unroll
    for (int g = 1; g <= 9; ++g) {
        stage2(g);
        __pipeline_wait_prior(1);
        consume((g - 1) & 1, acc2);
    }
    stage3(0);                         // g=10, parity 0
    __pipeline_wait_prior(1);
    consume(1, acc2);                  // group 9
#pragma unroll
    for (int t = 1; t <= 3; ++t) {
        stage3(t);
        __pipeline_wait_prior(1);
        consume((t - 1) & 1, acc3);    // matches stage3(t-1) parity
    }
    __pipeline_wait_prior(0);
    consume(1, acc3);                  // group t=3, parity 1

    // ---------- finalize v2 / v3 / feats ----------
    if (lane < 20) {
        float4 r2 = make_float4(acc2.x * 0.02f, acc2.y * 0.02f, acc2.z * 0.02f, acc2.w * 0.02f);
        float4 r3 = make_float4(acc3.x * 0.05f, acc3.y * 0.05f, acc3.z * 0.05f, acc3.w * 0.05f);
        *(float4*)(v + 2 * 80 + lane * 4) = r2;
        *(float4*)(v + 3 * 80 + lane * 4) = r3;
    }
    float p2 = (lane >= 24) ? l2acc : 0.f;
    float p3 = (lane >= 24) ? l3acc : 0.f;
#pragma unroll
    for (int off = 16; off; off >>= 1) {
        p2 += __shfl_xor_sync(0xffffffffu, p2, off);
        p3 += __shfl_xor_sync(0xffffffffu, p3, off);
    }
    if (lane == 0) { feat[2] = p2 * 0.02f; feat[3] = p3 * 0.05f; }
    __syncwarp();

    // ---------- pair interactions: 15 pairs x 4 chunks = 60 items ----------
    float partial = 0.f;
#pragma unroll
    for (int r = 0; r < 2; ++r) {
        const int item = lane + r * 32;
        if (item < 60) {
            const int t = item >> 2;
            const int c = item & 3;
            const int i = c_pair_i[t];
            const int j = c_pair_j[t];
            const float4 a  = *(const float4*)(v + i * 80 + (j - 1) * 16 + c * 4);
            const float4 bb = *(const float4*)(v + j * 80 +  i      * 16 + c * 4);
            partial += a.x * bb.x + a.y * bb.y + a.z * bb.z + a.w * bb.w;
        }
    }
#pragma unroll
    for (int off = 16; off; off >>= 1)
        partial += __shfl_xor_sync(0xffffffffu, partial, off);

    if (lane == 0) {
        float lin = __ldg(bd);
#pragma unroll
        for (int i = 0; i < 6; ++i) lin += feat[i] * __ldg(Wd + i);
        lin = fmaxf(lin, 0.f);
        out[b] = 1.0f / (1.0f + expf(-(lin + partial)));
    }
}

extern "C" void kernel_launch(void* const* d_in, const int* in_sizes, int n_in,
                              void* d_out, int out_size)
{
    const int* xs[6];
    for (int i = 0; i < 6; ++i) xs[i] = (const int*)d_in[i];

    // Classify E/L by element count (robust to input ordering):
    // E_i has 80*DIM_i elements, L_i has DIM_i. Disjoint size sets.
    const float* E[6] = {0,0,0,0,0,0};
    const float* L[6] = {0,0,0,0,0,0};
    const float* Wd = 0;
    const float* bd = 0;
    int ei = 0, li = 0;
    for (int k = 6; k < n_in; ++k) {
        const long long sz = (long long)in_sizes[k];
        const float* p = (const float*)d_in[k];
        if (sz == 80000000LL || sz == 40000000LL || sz == 8000000LL ||
            sz == 800000LL   || sz == 80000LL) {
            if (ei < 6) E[ei++] = p;
        } else if (sz == 1000000LL || sz == 500000LL || sz == 100000LL ||
                   sz == 10000LL   || sz == 1000LL) {
            if (li < 6) L[li++] = p;
        } else if (sz == 6LL) {
            Wd = p;
        } else if (sz == 1LL) {
            bd = p;
        }
    }

    float* out = (float*)d_out;
    const int blocks = BATCH / WPB; // 2048
    ffm_kernel<<<blocks, WPB * 32>>>(
        xs[0], xs[1], xs[2], xs[3], xs[4], xs[5],
        E[0], E[1], E[2], E[3], E[4], E[5],
        L[0], L[1], L[2], L[3], L[4], L[5],
        Wd, bd, out);
}